// round 1
// baseline (speedup 1.0000x reference)
#include <cuda_runtime.h>
#include <math.h>
#include <stdint.h>

#define NC 21
#define MAXN 8732
#define MAXB 128
#define OBJ 16

// ---------------- device scratch (no allocations allowed) ----------------
__device__ double g_loss_l;
__device__ double g_loss_c;
__device__ int    g_npos_total;
__device__ int    g_npos_b[MAXB];
__device__ float  g_lc [MAXB * MAXN];
__device__ unsigned char g_cls[MAXB * MAXN];
__device__ unsigned char g_bti[MAXB * MAXN];

// ---------------- init ----------------
__global__ void init_kernel() {
    int t = threadIdx.x;
    if (t == 0) { g_loss_l = 0.0; g_loss_c = 0.0; g_npos_total = 0; }
    for (int b = t; b < MAXB; b += blockDim.x) g_npos_b[b] = 0;
}

// ---------------- matching: one CTA per batch ----------------
__global__ void match_kernel(const float* __restrict__ targets,
                             const float* __restrict__ priors,
                             int N) {
    int b   = blockIdx.x;
    int tid = threadIdx.x;

    __shared__ float s_t[OBJ * 4];
    __shared__ float s_area[OBJ];
    __shared__ int   s_lab[OBJ];
    __shared__ unsigned long long s_key[OBJ];
    __shared__ float s_bto[MAXN];
    __shared__ unsigned char s_bti[MAXN];

    if (tid < OBJ) {
        const float* tr = targets + ((size_t)b * OBJ + tid) * 5;
        float x1 = tr[0], y1 = tr[1], x2 = tr[2], y2 = tr[3];
        s_t[tid*4+0] = x1; s_t[tid*4+1] = y1;
        s_t[tid*4+2] = x2; s_t[tid*4+3] = y2;
        s_area[tid] = (x2 - x1) * (y2 - y1);
        s_lab[tid]  = (int)tr[4];
        s_key[tid]  = 0ULL;
    }
    __syncthreads();

    // per-thread local best key per truth: (iou_bits << 32) | (~i) -> max picks
    // largest IoU, smallest index on exact ties (matches jnp.argmax first-max).
    unsigned long long lkey[OBJ];
    #pragma unroll
    for (int j = 0; j < OBJ; j++) lkey[j] = 0ULL;

    for (int i = tid; i < N; i += blockDim.x) {
        float4 p = ((const float4*)priors)[i];
        float px1 = p.x - p.z * 0.5f, py1 = p.y - p.w * 0.5f;
        float px2 = p.x + p.z * 0.5f, py2 = p.y + p.w * 0.5f;
        float parea = (px2 - px1) * (py2 - py1);

        float best = -1.0f; int bj = 0;
        #pragma unroll
        for (int j = 0; j < OBJ; j++) {
            float ix = fminf(s_t[j*4+2], px2) - fmaxf(s_t[j*4+0], px1);
            float iy = fminf(s_t[j*4+3], py2) - fmaxf(s_t[j*4+1], py1);
            ix = fmaxf(ix, 0.0f); iy = fmaxf(iy, 0.0f);
            float inter = ix * iy;
            float iou = inter / (s_area[j] + parea - inter);
            if (iou > best) { best = iou; bj = j; }  // strict > = first max over j
            unsigned long long key =
                (((unsigned long long)__float_as_uint(iou)) << 32) |
                (unsigned long long)(0xFFFFFFFFu - (unsigned)i);
            if (key > lkey[j]) lkey[j] = key;
        }
        s_bto[i] = best;
        s_bti[i] = (unsigned char)bj;
    }
    #pragma unroll
    for (int j = 0; j < OBJ; j++) atomicMax(&s_key[j], lkey[j]);
    __syncthreads();

    // forced matches: overlap := 2.0, idx := j (later j wins, same as fori_loop)
    if (tid == 0) {
        for (int j = 0; j < OBJ; j++) {
            unsigned idx = 0xFFFFFFFFu - (unsigned)(s_key[j] & 0xFFFFFFFFu);
            s_bto[idx] = 2.0f;
            s_bti[idx] = (unsigned char)j;
        }
    }
    __syncthreads();

    for (int i = tid; i < N; i += blockDim.x) {
        int tj  = s_bti[i];
        int cls = (s_bto[i] < 0.5f) ? 0 : (s_lab[tj] + 1);
        g_cls[(size_t)b * N + i] = (unsigned char)cls;
        g_bti[(size_t)b * N + i] = (unsigned char)tj;
    }
}

// ---------------- per-prior losses: grid (N/256, B) ----------------
__global__ void loss_kernel(const float* __restrict__ loc,
                            const float* __restrict__ conf,
                            const float* __restrict__ targets,
                            const float* __restrict__ priors,
                            int N) {
    int b   = blockIdx.y;
    int i0  = blockIdx.x * 256;
    int tid = threadIdx.x;
    int i   = i0 + tid;

    __shared__ float s_conf[256 * NC];
    __shared__ double s_red[256];
    __shared__ int    s_icnt[256];

    int cnt = min(256, N - i0);
    const float* src = conf + ((size_t)b * N + i0) * NC;
    for (int k = tid; k < cnt * NC; k += 256) s_conf[k] = src[k];
    __syncthreads();

    double ll = 0.0, lcpos = 0.0;
    int np = 0;

    if (i < N) {
        size_t gi = (size_t)b * N + i;
        int cls = g_cls[gi];
        const float* row = s_conf + tid * NC;
        float m = row[0];
        #pragma unroll
        for (int c = 1; c < NC; c++) m = fmaxf(m, row[c]);
        float s = 0.0f;
        #pragma unroll
        for (int c = 0; c < NC; c++) s += expf(row[c] - m);
        float lse = m + logf(s);
        float lca = lse - row[cls];
        bool pos = (cls > 0);
        g_lc[gi] = pos ? 0.0f : lca;

        if (pos) {
            lcpos = (double)lca;
            np = 1;
            int tj = g_bti[gi];
            const float* tr = targets + ((size_t)b * OBJ + tj) * 5;
            float4 p = ((const float4*)priors)[i];
            float gx = ((tr[0] + tr[2]) * 0.5f - p.x) / (0.1f * p.z);
            float gy = ((tr[1] + tr[3]) * 0.5f - p.y) / (0.1f * p.w);
            float gw = logf((tr[2] - tr[0]) / p.z) / 0.2f;
            float gh = logf((tr[3] - tr[1]) / p.w) / 0.2f;
            float4 l = ((const float4*)loc)[gi];
            float d;
            d = l.x - gx; ll += (fabsf(d) < 1.0f) ? 0.5f*d*d : fabsf(d) - 0.5f;
            d = l.y - gy; ll += (fabsf(d) < 1.0f) ? 0.5f*d*d : fabsf(d) - 0.5f;
            d = l.z - gw; ll += (fabsf(d) < 1.0f) ? 0.5f*d*d : fabsf(d) - 0.5f;
            d = l.w - gh; ll += (fabsf(d) < 1.0f) ? 0.5f*d*d : fabsf(d) - 0.5f;
        }
    }

    // reductions
    s_red[tid] = ll; __syncthreads();
    for (int s = 128; s > 0; s >>= 1) { if (tid < s) s_red[tid] += s_red[tid + s]; __syncthreads(); }
    if (tid == 0) atomicAdd(&g_loss_l, s_red[0]);
    __syncthreads();

    s_red[tid] = lcpos; __syncthreads();
    for (int s = 128; s > 0; s >>= 1) { if (tid < s) s_red[tid] += s_red[tid + s]; __syncthreads(); }
    if (tid == 0) atomicAdd(&g_loss_c, s_red[0]);
    __syncthreads();

    s_icnt[tid] = np; __syncthreads();
    for (int s = 128; s > 0; s >>= 1) { if (tid < s) s_icnt[tid] += s_icnt[tid + s]; __syncthreads(); }
    if (tid == 0) {
        atomicAdd(&g_npos_total, s_icnt[0]);
        atomicAdd(&g_npos_b[b], s_icnt[0]);
    }
}

// ---------------- hard-negative mining: radix top-K per batch ----------------
__global__ void select_kernel(int N) {
    int b   = blockIdx.x;
    int tid = threadIdx.x;

    __shared__ unsigned s_u[MAXN];
    __shared__ unsigned s_hist[256];
    __shared__ unsigned s_prefix;
    __shared__ unsigned s_remK;
    __shared__ double   s_red[256];
    __shared__ unsigned s_cnt[256];

    for (int i = tid; i < N; i += 256)
        s_u[i] = __float_as_uint(g_lc[(size_t)b * N + i]);  // lc >= 0 -> monotone bits

    int K = min(3 * g_npos_b[b], N - 1);
    if (K <= 0) return;  // uniform across the block

    if (tid == 0) { s_prefix = 0u; s_remK = (unsigned)K; }
    __syncthreads();

    for (int pass = 0; pass < 4; pass++) {
        int shift = 24 - pass * 8;
        unsigned maskAbove = (pass == 0) ? 0u : (0xFFFFFFFFu << (shift + 8));
        for (int k = tid; k < 256; k += 256) s_hist[k] = 0u;
        __syncthreads();
        unsigned prefix = s_prefix;
        for (int i = tid; i < N; i += 256) {
            unsigned u = s_u[i];
            if ((u & maskAbove) == prefix)
                atomicAdd(&s_hist[(u >> shift) & 255u], 1u);
        }
        __syncthreads();
        if (tid == 0) {
            unsigned acc = 0; int selb = 0;
            for (int bin = 255; bin >= 0; bin--) {
                unsigned h = s_hist[bin];
                if (acc + h >= s_remK) { selb = bin; s_remK -= acc; break; }
                acc += h;
            }
            s_prefix = prefix | ((unsigned)selb << shift);
        }
        __syncthreads();
    }

    unsigned tbits = s_prefix;           // bits of the K-th largest value
    double lsum = 0.0; unsigned cgt = 0;
    for (int i = tid; i < N; i += 256) {
        unsigned u = s_u[i];
        if (u > tbits) { lsum += (double)__uint_as_float(u); cgt++; }
    }
    s_red[tid] = lsum; s_cnt[tid] = cgt; __syncthreads();
    for (int s = 128; s > 0; s >>= 1) {
        if (tid < s) { s_red[tid] += s_red[tid + s]; s_cnt[tid] += s_cnt[tid + s]; }
        __syncthreads();
    }
    if (tid == 0) {
        unsigned m = (unsigned)K - s_cnt[0];  // tie slots, all worth exactly t
        double total = s_red[0] + (double)m * (double)__uint_as_float(tbits);
        atomicAdd(&g_loss_c, total);
    }
}

// ---------------- finalize ----------------
__global__ void fin_kernel(float* out) {
    float n = (float)g_npos_total;
    out[0] = (float)g_loss_l / n;
    out[1] = (float)g_loss_c / n;
}

// ---------------- launch ----------------
extern "C" void kernel_launch(void* const* d_in, const int* in_sizes, int n_in,
                              void* d_out, int out_size) {
    const float* loc     = (const float*)d_in[0];
    const float* conf    = (const float*)d_in[1];
    const float* targets = (const float*)d_in[2];
    const float* priors  = (const float*)d_in[3];
    int N = in_sizes[3] / 4;
    int B = in_sizes[0] / (4 * N);

    init_kernel<<<1, 128>>>();
    match_kernel<<<B, 256>>>(targets, priors, N);
    dim3 g((N + 255) / 256, B);
    loss_kernel<<<g, 256>>>(loc, conf, targets, priors, N);
    select_kernel<<<B, 256>>>(N);
    fin_kernel<<<1, 1>>>((float*)d_out);
}

// round 2
// speedup vs baseline: 1.4421x; 1.4421x over previous
#include <cuda_runtime.h>
#include <math.h>
#include <stdint.h>

#define NC 21
#define MAXN 8732
#define MAXB 128
#define OBJ 16
#define FULLW 0xffffffffu

// ---------------- device scratch (no allocations allowed) ----------------
__device__ double g_loss_l;
__device__ double g_loss_c;
__device__ int    g_npos_total;
__device__ int    g_npos_b[MAXB];
__device__ float  g_lc [MAXB * MAXN];
__device__ unsigned char g_cls[MAXB * MAXN];
__device__ unsigned char g_bti[MAXB * MAXN];

// ---------------- init ----------------
__global__ void init_kernel() {
    int t = threadIdx.x;
    if (t == 0) { g_loss_l = 0.0; g_loss_c = 0.0; g_npos_total = 0; }
    for (int b = t; b < MAXB; b += blockDim.x) g_npos_b[b] = 0;
}

// ---------------- matching: one CTA (1024 thr) per batch ----------------
__global__ void __launch_bounds__(1024) match_kernel(
        const float* __restrict__ targets,
        const float* __restrict__ priors,
        int N) {
    int b    = blockIdx.x;
    int tid  = threadIdx.x;
    int lane = tid & 31;

    __shared__ float s_t[OBJ * 4];
    __shared__ float s_area[OBJ];
    __shared__ int   s_lab[OBJ];
    __shared__ unsigned long long s_key[OBJ];
    __shared__ float s_bto[MAXN];
    __shared__ unsigned char s_bti[MAXN];

    if (tid < OBJ) {
        const float* tr = targets + ((size_t)b * OBJ + tid) * 5;
        float x1 = tr[0], y1 = tr[1], x2 = tr[2], y2 = tr[3];
        s_t[tid*4+0] = x1; s_t[tid*4+1] = y1;
        s_t[tid*4+2] = x2; s_t[tid*4+3] = y2;
        s_area[tid] = (x2 - x1) * (y2 - y1);
        s_lab[tid]  = (int)tr[4];
        s_key[tid]  = 0ULL;
    }
    __syncthreads();

    // local best key per truth: (iou_bits<<32)|(~i) -> max = largest IoU,
    // smallest index on ties (== jnp.argmax first-max semantics).
    unsigned long long lkey[OBJ];
    #pragma unroll
    for (int j = 0; j < OBJ; j++) lkey[j] = 0ULL;

    for (int i = tid; i < N; i += 1024) {
        float4 p = ((const float4*)priors)[i];
        float px1 = p.x - p.z * 0.5f, py1 = p.y - p.w * 0.5f;
        float px2 = p.x + p.z * 0.5f, py2 = p.y + p.w * 0.5f;
        float parea = (px2 - px1) * (py2 - py1);

        float best = -1.0f; int bj = 0;
        #pragma unroll
        for (int j = 0; j < OBJ; j++) {
            float ix = fminf(s_t[j*4+2], px2) - fmaxf(s_t[j*4+0], px1);
            float iy = fminf(s_t[j*4+3], py2) - fmaxf(s_t[j*4+1], py1);
            ix = fmaxf(ix, 0.0f); iy = fmaxf(iy, 0.0f);
            float inter = ix * iy;
            float iou = __fdividef(inter, s_area[j] + parea - inter);
            if (iou > best) { best = iou; bj = j; }   // strict > = first max over j
            unsigned long long key =
                (((unsigned long long)__float_as_uint(iou)) << 32) |
                (unsigned long long)(0xFFFFFFFFu - (unsigned)i);
            if (key > lkey[j]) lkey[j] = key;
        }
        s_bto[i] = best;
        s_bti[i] = (unsigned char)bj;
    }

    // warp-reduce keys, then one smem atomic per warp per truth
    #pragma unroll
    for (int j = 0; j < OBJ; j++) {
        unsigned long long k = lkey[j];
        #pragma unroll
        for (int off = 16; off > 0; off >>= 1) {
            unsigned long long o = __shfl_down_sync(FULLW, k, off);
            if (o > k) k = o;
        }
        if (lane == 0) atomicMax(&s_key[j], k);
    }
    __syncthreads();

    // forced matches (serial, 16 iters; later j wins == fori_loop)
    if (tid == 0) {
        #pragma unroll
        for (int j = 0; j < OBJ; j++) {
            unsigned idx = 0xFFFFFFFFu - (unsigned)(s_key[j] & 0xFFFFFFFFu);
            s_bto[idx] = 2.0f;
            s_bti[idx] = (unsigned char)j;
        }
    }
    __syncthreads();

    for (int i = tid; i < N; i += 1024) {
        int tj  = s_bti[i];
        int cls = (s_bto[i] < 0.5f) ? 0 : (s_lab[tj] + 1);
        g_cls[(size_t)b * N + i] = (unsigned char)cls;
        g_bti[(size_t)b * N + i] = (unsigned char)tj;
    }
}

// ---------------- per-prior losses: grid (N/256, B) ----------------
__global__ void __launch_bounds__(256) loss_kernel(
        const float* __restrict__ loc,
        const float* __restrict__ conf,
        const float* __restrict__ targets,
        const float* __restrict__ priors,
        int N) {
    int b    = blockIdx.y;
    int i0   = blockIdx.x * 256;
    int tid  = threadIdx.x;
    int i    = i0 + tid;
    int lane = tid & 31;
    int warp = tid >> 5;

    __shared__ float  s_conf[256 * NC];
    __shared__ double s_dll[8], s_dlc[8];
    __shared__ int    s_np[8];

    int cnt  = min(256, N - i0);
    int nfl  = cnt * NC;
    {   // float4 staging (cnt*21 is always divisible by 4 here; guard anyway)
        const float*  src  = conf + ((size_t)b * N + i0) * NC;
        const float4* src4 = (const float4*)src;
        float4* dst4 = (float4*)s_conf;
        int n4 = nfl >> 2;
        for (int k = tid; k < n4; k += 256) dst4[k] = src4[k];
        for (int k = (n4 << 2) + tid; k < nfl; k += 256) s_conf[k] = src[k];
    }
    __syncthreads();

    double ll = 0.0, lcpos = 0.0;
    int np = 0;

    if (i < N) {
        size_t gi = (size_t)b * N + i;
        int cls = g_cls[gi];
        const float* row = s_conf + tid * NC;
        float m = row[0];
        #pragma unroll
        for (int c = 1; c < NC; c++) m = fmaxf(m, row[c]);
        float s = 0.0f;
        #pragma unroll
        for (int c = 0; c < NC; c++) s += __expf(row[c] - m);
        float lse = m + __logf(s);
        float lca = lse - row[cls];
        bool pos = (cls > 0);
        g_lc[gi] = pos ? 0.0f : lca;

        if (pos) {
            lcpos = (double)lca;
            np = 1;
            int tj = g_bti[gi];
            const float* tr = targets + ((size_t)b * OBJ + tj) * 5;
            float4 p = ((const float4*)priors)[i];
            float gx = ((tr[0] + tr[2]) * 0.5f - p.x) / (0.1f * p.z);
            float gy = ((tr[1] + tr[3]) * 0.5f - p.y) / (0.1f * p.w);
            float gw = logf((tr[2] - tr[0]) / p.z) * 5.0f;
            float gh = logf((tr[3] - tr[1]) / p.w) * 5.0f;
            float4 l = ((const float4*)loc)[gi];
            float d;
            d = l.x - gx; ll += (fabsf(d) < 1.0f) ? 0.5f*d*d : fabsf(d) - 0.5f;
            d = l.y - gy; ll += (fabsf(d) < 1.0f) ? 0.5f*d*d : fabsf(d) - 0.5f;
            d = l.z - gw; ll += (fabsf(d) < 1.0f) ? 0.5f*d*d : fabsf(d) - 0.5f;
            d = l.w - gh; ll += (fabsf(d) < 1.0f) ? 0.5f*d*d : fabsf(d) - 0.5f;
        }
    }

    // fused warp-shuffle reduction, 1 barrier
    #pragma unroll
    for (int off = 16; off > 0; off >>= 1) {
        ll    += __shfl_down_sync(FULLW, ll,    off);
        lcpos += __shfl_down_sync(FULLW, lcpos, off);
        np    += __shfl_down_sync(FULLW, np,    off);
    }
    if (lane == 0) { s_dll[warp] = ll; s_dlc[warp] = lcpos; s_np[warp] = np; }
    __syncthreads();
    if (warp == 0) {
        double a = (lane < 8) ? s_dll[lane] : 0.0;
        double c = (lane < 8) ? s_dlc[lane] : 0.0;
        int    n = (lane < 8) ? s_np[lane]  : 0;
        #pragma unroll
        for (int off = 4; off > 0; off >>= 1) {
            a += __shfl_down_sync(FULLW, a, off);
            c += __shfl_down_sync(FULLW, c, off);
            n += __shfl_down_sync(FULLW, n, off);
        }
        if (lane == 0) {
            if (a != 0.0) atomicAdd(&g_loss_l, a);
            if (c != 0.0) atomicAdd(&g_loss_c, c);
            if (n)        { atomicAdd(&g_npos_total, n); atomicAdd(&g_npos_b[b], n); }
        }
    }
}

// ---------------- hard-negative mining: radix top-K, 1024 thr/batch --------
__global__ void __launch_bounds__(1024) select_kernel(int N) {
    int b    = blockIdx.x;
    int tid  = threadIdx.x;
    int lane = tid & 31;
    int warp = tid >> 5;

    __shared__ unsigned s_u[MAXN];
    __shared__ unsigned s_hist[256];
    __shared__ unsigned s_prefix;
    __shared__ unsigned s_remK;
    __shared__ double   s_d[32];
    __shared__ unsigned s_c[32];

    {   // vectorized load (N = 8732 divisible by 4)
        const uint4* src4 = (const uint4*)((const unsigned*)g_lc + (size_t)b * N);
        uint4* dst4 = (uint4*)s_u;
        int n4 = N >> 2;
        for (int k = tid; k < n4; k += 1024) dst4[k] = src4[k];
        for (int k = (n4 << 2) + tid; k < N; k += 1024)
            s_u[k] = __float_as_uint(g_lc[(size_t)b * N + k]);
    }

    int K = min(3 * g_npos_b[b], N - 1);
    if (K <= 0) return;  // uniform across block

    if (tid == 0) { s_prefix = 0u; s_remK = (unsigned)K; }
    __syncthreads();

    #pragma unroll
    for (int pass = 0; pass < 4; pass++) {
        int shift = 24 - pass * 8;
        unsigned maskAbove = (pass == 0) ? 0u : (0xFFFFFFFFu << (shift + 8));
        if (tid < 256) s_hist[tid] = 0u;
        __syncthreads();
        unsigned prefix = s_prefix;
        for (int i = tid; i < N; i += 1024) {
            unsigned u = s_u[i];
            if ((u & maskAbove) == prefix)
                atomicAdd(&s_hist[(u >> shift) & 255u], 1u);
        }
        __syncthreads();
        // warp-0 register suffix scan over 256 bins (8 bins/lane)
        if (tid < 32) {
            unsigned h[8]; unsigned lsum = 0;
            #pragma unroll
            for (int k = 0; k < 8; k++) { h[k] = s_hist[tid * 8 + k]; lsum += h[k]; }
            unsigned suf = lsum;                    // will hold sum over lanes >= tid
            #pragma unroll
            for (int off = 1; off < 32; off <<= 1) {
                unsigned v = __shfl_down_sync(FULLW, suf, off);
                if (tid + off < 32) suf += v;
            }
            unsigned remK = s_remK;
            unsigned acc = suf - lsum;              // count in lanes > tid (higher bins)
            #pragma unroll
            for (int k = 7; k >= 0; k--) {          // high bin -> low within lane
                if (acc < remK && acc + h[k] >= remK) {
                    s_prefix = prefix | ((unsigned)(tid * 8 + k) << shift);
                    s_remK   = remK - acc;
                }
                acc += h[k];
            }
        }
        __syncthreads();
    }

    unsigned tbits = s_prefix;                      // bits of K-th largest value
    double lsum = 0.0; unsigned cgt = 0;
    for (int i = tid; i < N; i += 1024) {
        unsigned u = s_u[i];
        if (u > tbits) { lsum += (double)__uint_as_float(u); cgt++; }
    }
    #pragma unroll
    for (int off = 16; off > 0; off >>= 1) {
        lsum += __shfl_down_sync(FULLW, lsum, off);
        cgt  += __shfl_down_sync(FULLW, cgt,  off);
    }
    if (lane == 0) { s_d[warp] = lsum; s_c[warp] = cgt; }
    __syncthreads();
    if (warp == 0) {
        double a  = s_d[lane];
        unsigned c = s_c[lane];
        #pragma unroll
        for (int off = 16; off > 0; off >>= 1) {
            a += __shfl_down_sync(FULLW, a, off);
            c += __shfl_down_sync(FULLW, c, off);
        }
        if (lane == 0) {
            unsigned m = (unsigned)K - c;           // tie slots, each worth exactly t
            double total = a + (double)m * (double)__uint_as_float(tbits);
            atomicAdd(&g_loss_c, total);
        }
    }
}

// ---------------- finalize ----------------
__global__ void fin_kernel(float* out) {
    float n = (float)g_npos_total;
    out[0] = (float)g_loss_l / n;
    out[1] = (float)g_loss_c / n;
}

// ---------------- launch ----------------
extern "C" void kernel_launch(void* const* d_in, const int* in_sizes, int n_in,
                              void* d_out, int out_size) {
    const float* loc     = (const float*)d_in[0];
    const float* conf    = (const float*)d_in[1];
    const float* targets = (const float*)d_in[2];
    const float* priors  = (const float*)d_in[3];
    int N = in_sizes[3] / 4;
    int B = in_sizes[0] / (4 * N);

    init_kernel<<<1, 128>>>();
    match_kernel<<<B, 1024>>>(targets, priors, N);
    dim3 g((N + 255) / 256, B);
    loss_kernel<<<g, 256>>>(loc, conf, targets, priors, N);
    select_kernel<<<B, 1024>>>(N);
    fin_kernel<<<1, 1>>>((float*)d_out);
}

// round 3
// speedup vs baseline: 1.6820x; 1.1664x over previous
#include <cuda_runtime.h>
#include <math.h>
#include <stdint.h>

#define NC 21
#define MAXN 8732
#define OBJ 16
#define FULLW 0xffffffffu
#define TPB 1024

// -------- global accumulators (statically zeroed; last CTA resets them) ----
__device__ double   g_loss_l     = 0.0;
__device__ double   g_loss_c     = 0.0;
__device__ int      g_npos_total = 0;
__device__ unsigned g_ticket     = 0;

// dynamic smem layout:
//   s_conf : TPB*NC floats   (86016 B)  staging tile for conf rows
//   s_u    : MAXN  u32       (34928 B)  lc bits (0 for positives)
//   s_cls  : MAXN  u8        ( 8732 B)
//   s_bti  : MAXN  u8        ( 8732 B)
#define DYN_BYTES (TPB*NC*4 + MAXN*4 + MAXN + MAXN)

extern __shared__ unsigned char s_dyn[];

__global__ void __launch_bounds__(TPB, 1) fused_kernel(
        const float* __restrict__ loc,
        const float* __restrict__ conf,
        const float* __restrict__ targets,
        const float* __restrict__ priors,
        int N, int B, float* __restrict__ out)
{
    const int b    = blockIdx.x;
    const int tid  = threadIdx.x;
    const int lane = tid & 31;
    const int warp = tid >> 5;

    float*          s_conf = (float*)s_dyn;
    unsigned*       s_u    = (unsigned*)(s_dyn + TPB*NC*4);
    unsigned char*  s_cls  = (unsigned char*)(s_u + MAXN);
    unsigned char*  s_bti  = s_cls + MAXN;

    __shared__ float s_t[OBJ*4];
    __shared__ float s_area[OBJ];
    __shared__ int   s_lab[OBJ];
    __shared__ unsigned long long s_key[OBJ];
    __shared__ unsigned s_hist[256];
    __shared__ unsigned s_prefix, s_remK;
    __shared__ double s_rd[32], s_rd2[32];
    __shared__ int    s_ri[32];
    __shared__ int    s_npb;

    // ================= phase 1: match =================
    if (tid < OBJ) {
        const float* tr = targets + ((size_t)b * OBJ + tid) * 5;
        float x1 = tr[0], y1 = tr[1], x2 = tr[2], y2 = tr[3];
        s_t[tid*4+0] = x1; s_t[tid*4+1] = y1;
        s_t[tid*4+2] = x2; s_t[tid*4+3] = y2;
        s_area[tid] = (x2 - x1) * (y2 - y1);
        s_lab[tid]  = (int)tr[4];
        s_key[tid]  = 0ULL;
    }
    __syncthreads();

    {
        // per-truth best key: (iou_bits<<32)|(~i) -> max = largest IoU,
        // smallest prior index on ties (== jnp.argmax first-max).
        unsigned long long lkey[OBJ];
        #pragma unroll
        for (int j = 0; j < OBJ; j++) lkey[j] = 0ULL;

        for (int i = tid; i < N; i += TPB) {
            float4 p = ((const float4*)priors)[i];
            float px1 = p.x - p.z * 0.5f, py1 = p.y - p.w * 0.5f;
            float px2 = p.x + p.z * 0.5f, py2 = p.y + p.w * 0.5f;
            float parea = (px2 - px1) * (py2 - py1);

            float best = -1.0f; int bj = 0;
            #pragma unroll
            for (int j = 0; j < OBJ; j++) {
                float ix = fminf(s_t[j*4+2], px2) - fmaxf(s_t[j*4+0], px1);
                float iy = fminf(s_t[j*4+3], py2) - fmaxf(s_t[j*4+1], py1);
                ix = fmaxf(ix, 0.0f); iy = fmaxf(iy, 0.0f);
                float inter = ix * iy;
                float iou = __fdividef(inter, s_area[j] + parea - inter);
                if (iou > best) { best = iou; bj = j; }  // strict > = first max
                unsigned long long key =
                    (((unsigned long long)__float_as_uint(iou)) << 32) |
                    (unsigned long long)(0xFFFFFFFFu - (unsigned)i);
                if (key > lkey[j]) lkey[j] = key;
            }
            s_cls[i] = (best < 0.5f) ? 0 : (unsigned char)(s_lab[bj] + 1);
            s_bti[i] = (unsigned char)bj;
        }

        #pragma unroll
        for (int j = 0; j < OBJ; j++) {
            unsigned long long k = lkey[j];
            #pragma unroll
            for (int off = 16; off > 0; off >>= 1) {
                unsigned long long o = __shfl_down_sync(FULLW, k, off);
                if (o > k) k = o;
            }
            if (lane == 0) atomicMax(&s_key[j], k);
        }
    }
    __syncthreads();

    // forced matches: overlap:=2.0 (>=0.5 so cls forced), later j wins.
    if (tid == 0) {
        #pragma unroll
        for (int j = 0; j < OBJ; j++) {
            unsigned idx = 0xFFFFFFFFu - (unsigned)(s_key[j] & 0xFFFFFFFFu);
            s_cls[idx] = (unsigned char)(s_lab[j] + 1);
            s_bti[idx] = (unsigned char)j;
        }
    }
    __syncthreads();

    // ================= phase 2: per-prior losses (stream conf) =============
    double ll = 0.0, lcp = 0.0; int np = 0;

    for (int t0 = 0; t0 < N; t0 += TPB) {
        int cnt = min(TPB, N - t0);
        int nfl = cnt * NC;
        const float* src = conf + ((size_t)b * N + t0) * NC;
        {   // float4 staging (offsets are 16B-aligned: N*NC and TPB*NC div by 4)
            const float4* s4 = (const float4*)src;
            float4* d4 = (float4*)s_conf;
            int n4 = nfl >> 2;
            for (int k = tid; k < n4; k += TPB) d4[k] = s4[k];
            for (int k = (n4 << 2) + tid; k < nfl; k += TPB) s_conf[k] = src[k];
        }
        __syncthreads();

        if (tid < cnt) {
            int i = t0 + tid;
            int cls = s_cls[i];
            const float* row = s_conf + tid * NC;   // stride 21: bank-conflict-free
            float m = row[0];
            #pragma unroll
            for (int c = 1; c < NC; c++) m = fmaxf(m, row[c]);
            float s = 0.0f;
            #pragma unroll
            for (int c = 0; c < NC; c++) s += __expf(row[c] - m);
            float lse = m + __logf(s);
            float lca = lse - row[cls];
            bool pos = (cls > 0);
            s_u[i] = pos ? 0u : __float_as_uint(lca);   // lc >= 0: monotone bits

            if (pos) {
                lcp += (double)lca; np++;
                int tj = s_bti[i];
                float tx1 = s_t[tj*4+0], ty1 = s_t[tj*4+1];
                float tx2 = s_t[tj*4+2], ty2 = s_t[tj*4+3];
                float4 p = ((const float4*)priors)[i];
                float gx = ((tx1 + tx2) * 0.5f - p.x) / (0.1f * p.z);
                float gy = ((ty1 + ty2) * 0.5f - p.y) / (0.1f * p.w);
                float gw = logf((tx2 - tx1) / p.z) * 5.0f;
                float gh = logf((ty2 - ty1) / p.w) * 5.0f;
                float4 l = ((const float4*)loc)[(size_t)b * N + i];
                float d;
                d = l.x - gx; ll += (fabsf(d) < 1.0f) ? 0.5f*d*d : fabsf(d) - 0.5f;
                d = l.y - gy; ll += (fabsf(d) < 1.0f) ? 0.5f*d*d : fabsf(d) - 0.5f;
                d = l.z - gw; ll += (fabsf(d) < 1.0f) ? 0.5f*d*d : fabsf(d) - 0.5f;
                d = l.w - gh; ll += (fabsf(d) < 1.0f) ? 0.5f*d*d : fabsf(d) - 0.5f;
            }
        }
        __syncthreads();
    }

    // block reduce (ll, lcp, np)
    #pragma unroll
    for (int off = 16; off > 0; off >>= 1) {
        ll  += __shfl_down_sync(FULLW, ll,  off);
        lcp += __shfl_down_sync(FULLW, lcp, off);
        np  += __shfl_down_sync(FULLW, np,  off);
    }
    if (lane == 0) { s_rd[warp] = ll; s_rd2[warp] = lcp; s_ri[warp] = np; }
    __syncthreads();

    double bll = 0.0, blc = 0.0; int bnp = 0;
    if (warp == 0) {
        bll = s_rd[lane]; blc = s_rd2[lane]; bnp = s_ri[lane];
        #pragma unroll
        for (int off = 16; off > 0; off >>= 1) {
            bll += __shfl_down_sync(FULLW, bll, off);
            blc += __shfl_down_sync(FULLW, blc, off);
            bnp += __shfl_down_sync(FULLW, bnp, off);
        }
        if (lane == 0) s_npb = bnp;
    }
    __syncthreads();

    int npb = s_npb;
    int K = min(3 * npb, N - 1);

    // ================= phase 3: hard-negative radix top-K on smem ==========
    double negsum = 0.0;   // valid on tid 0 after this phase

    if (K > 0) {
        if (tid == 0) { s_prefix = 0u; s_remK = (unsigned)K; }
        __syncthreads();

        const int iters = (N + TPB - 1) / TPB;
        #pragma unroll
        for (int pass = 0; pass < 4; pass++) {
            int shift = 24 - pass * 8;
            unsigned maskAbove = (pass == 0) ? 0u : (0xFFFFFFFFu << (shift + 8));
            if (tid < 256) s_hist[tid] = 0u;
            __syncthreads();
            unsigned prefix = s_prefix;
            for (int it = 0; it < iters; it++) {
                int i = it * TPB + tid;
                unsigned u = (i < N) ? s_u[i] : 0u;
                bool act = (i < N) && ((u & maskAbove) == prefix);
                unsigned amask = __ballot_sync(FULLW, act);
                if (act) {
                    unsigned bin = (u >> shift) & 255u;
                    unsigned mm = __match_any_sync(amask, bin);  // warp-aggregate
                    if (lane == (__ffs(mm) - 1))
                        atomicAdd(&s_hist[bin], (unsigned)__popc(mm));
                }
            }
            __syncthreads();
            // warp-0 register suffix scan over 256 bins (8 bins/lane)
            if (tid < 32) {
                unsigned h[8]; unsigned lsum = 0;
                #pragma unroll
                for (int k = 0; k < 8; k++) { h[k] = s_hist[tid*8 + k]; lsum += h[k]; }
                unsigned suf = lsum;
                #pragma unroll
                for (int off = 1; off < 32; off <<= 1) {
                    unsigned v = __shfl_down_sync(FULLW, suf, off);
                    if (tid + off < 32) suf += v;
                }
                unsigned remK = s_remK;
                unsigned acc = suf - lsum;        // count in higher bins
                #pragma unroll
                for (int k = 7; k >= 0; k--) {
                    if (acc < remK && acc + h[k] >= remK) {
                        s_prefix = prefix | ((unsigned)(tid*8 + k) << shift);
                        s_remK   = remK - acc;
                    }
                    acc += h[k];
                }
            }
            __syncthreads();
        }

        unsigned tbits = s_prefix;                // K-th largest value bits
        double lsum = 0.0; unsigned cgt = 0;
        for (int i = tid; i < N; i += TPB) {
            unsigned u = s_u[i];
            if (u > tbits) { lsum += (double)__uint_as_float(u); cgt++; }
        }
        #pragma unroll
        for (int off = 16; off > 0; off >>= 1) {
            lsum += __shfl_down_sync(FULLW, lsum, off);
            cgt  += __shfl_down_sync(FULLW, cgt,  off);
        }
        if (lane == 0) { s_rd[warp] = lsum; s_ri[warp] = (int)cgt; }
        __syncthreads();
        if (warp == 0) {
            double a = s_rd[lane];
            int    c = s_ri[lane];
            #pragma unroll
            for (int off = 16; off > 0; off >>= 1) {
                a += __shfl_down_sync(FULLW, a, off);
                c += __shfl_down_sync(FULLW, c, off);
            }
            if (lane == 0) {
                unsigned m = (unsigned)K - (unsigned)c;   // tie slots worth t each
                negsum = a + (double)m * (double)__uint_as_float(tbits);
            }
        }
    }

    // ================= phase 4: accumulate + self-finalize =================
    if (tid == 0) {
        atomicAdd(&g_loss_l, bll);
        atomicAdd(&g_loss_c, blc + negsum);
        atomicAdd(&g_npos_total, npb);
        __threadfence();
        unsigned t = atomicAdd(&g_ticket, 1u);
        if (t == (unsigned)B - 1u) {          // last CTA: finalize + reset
            __threadfence();
            double L = atomicAdd(&g_loss_l, 0.0);
            double C = atomicAdd(&g_loss_c, 0.0);
            int    n = atomicAdd(&g_npos_total, 0);
            float  nf = (float)n;
            out[0] = (float)L / nf;
            out[1] = (float)C / nf;
            g_loss_l = 0.0; g_loss_c = 0.0; g_npos_total = 0;
            __threadfence();
            g_ticket = 0u;
        }
    }
}

// ---------------- launch ----------------
extern "C" void kernel_launch(void* const* d_in, const int* in_sizes, int n_in,
                              void* d_out, int out_size) {
    const float* loc     = (const float*)d_in[0];
    const float* conf    = (const float*)d_in[1];
    const float* targets = (const float*)d_in[2];
    const float* priors  = (const float*)d_in[3];
    int N = in_sizes[3] / 4;
    int B = in_sizes[0] / (4 * N);

    cudaFuncSetAttribute(fused_kernel,
                         cudaFuncAttributeMaxDynamicSharedMemorySize, DYN_BYTES);
    fused_kernel<<<B, TPB, DYN_BYTES>>>(loc, conf, targets, priors, N, B,
                                        (float*)d_out);
}